// round 8
// baseline (speedup 1.0000x reference)
#include <cuda_runtime.h>
#include <cstdint>

#define PI  3.14159265358979323846f
#define PIH 1.57079632679489662f
#define IR2 0.70710678118654752f

// 16 MB scratch between passes (fits in L2)
__device__ float4 g_scr[1 << 20];

__device__ __forceinline__ float sin_ap(float x){ float y; asm("sin.approx.f32 %0, %1;" : "=f"(y) : "f"(x)); return y; }
__device__ __forceinline__ float sqrt_ap(float x){ float y; asm("sqrt.approx.f32 %0, %1;" : "=f"(y) : "f"(x)); return y; }
// conflict-free for float4 tiles at the strided patterns used
__device__ __forceinline__ int swz(int r){ return r ^ ((r >> 4) & 3) ^ (((r >> 5) & 3) << 2); }

// squared-magnitude butterfly; clamp product (tiny negatives from rounding)
__device__ __forceinline__ void bfly(float& Se, float& So, float c){
    float r  = sqrt_ap(fmaxf(Se * So, 0.f));
    float T  = c * r;
    float Sp = Se + So;
    Se = fmaf( 2.f, T, Sp);
    So = fmaf(-2.f, T, Sp);
}

struct Coef { float c1, cH, msH, q0, q1, q2, q3; };

// all radix-8 twiddles from quarter angle h4 = h1/4
__device__ __forceinline__ Coef mkcoef(float h4){
    Coef k;
    float s4 = sin_ap(h4), c4 = sin_ap(PIH - h4);
    float sH = 2.f * s4 * c4;
    float cH = fmaf(-2.f * s4, s4, 1.f);
    k.c1  = fmaf(2.f * cH, cH, -1.f);
    k.cH  = cH;  k.msH = -sH;
    k.q0  = c4;
    k.q1  = (c4 - s4) * IR2;
    k.q2  = -s4;
    k.q3  = -(c4 + s4) * IR2;
    return k;
}

// Pass A: stages pair ascending bits
__device__ __forceinline__ void r8A_apply(float* v, const Coef& k){
    bfly(v[0],v[1],k.c1);  bfly(v[2],v[3],k.c1);  bfly(v[4],v[5],k.c1);  bfly(v[6],v[7],k.c1);
    bfly(v[0],v[2],k.cH);  bfly(v[1],v[3],k.msH); bfly(v[4],v[6],k.cH);  bfly(v[5],v[7],k.msH);
    bfly(v[0],v[4],k.q0);  bfly(v[1],v[5],k.q1);  bfly(v[2],v[6],k.q2);  bfly(v[3],v[7],k.q3);
}
// Pass B: stages pair descending bits
__device__ __forceinline__ void r8B_apply(float* v, const Coef& k){
    bfly(v[0],v[4],k.c1);  bfly(v[1],v[5],k.c1);  bfly(v[2],v[6],k.c1);  bfly(v[3],v[7],k.c1);
    bfly(v[0],v[2],k.cH);  bfly(v[1],v[3],k.cH);  bfly(v[4],v[6],k.msH); bfly(v[5],v[7],k.msH);
    bfly(v[0],v[1],k.q0);  bfly(v[2],v[3],k.q2);  bfly(v[4],v[5],k.q1);  bfly(v[6],v[7],k.q3);
}

template<int B>
__device__ __forceinline__ void r8A(float4* tile, int t){
    const int   j0   = t & ((1 << B) - 1);
    const int   base = ((t >> B) << (B + 3)) | j0;
    const float h4   = (float)j0 * (PI / (float)(4 << B));
    Coef k = mkcoef(h4);
    int idx[8]; float4 v[8]; float a[8];
    #pragma unroll
    for (int n = 0; n < 8; n++){ idx[n] = swz(base + (n << B)); v[n] = tile[idx[n]]; }
    #pragma unroll
    for (int n = 0; n < 8; n++) a[n] = v[n].x;
    r8A_apply(a, k);
    #pragma unroll
    for (int n = 0; n < 8; n++){ v[n].x = a[n]; a[n] = v[n].y; }
    r8A_apply(a, k);
    #pragma unroll
    for (int n = 0; n < 8; n++){ v[n].y = a[n]; a[n] = v[n].z; }
    r8A_apply(a, k);
    #pragma unroll
    for (int n = 0; n < 8; n++){ v[n].z = a[n]; a[n] = v[n].w; }
    r8A_apply(a, k);
    #pragma unroll
    for (int n = 0; n < 8; n++){ v[n].w = a[n]; tile[idx[n]] = v[n]; }
}

// pass-B radix-8 on registers with per-lane twiddles
__device__ __forceinline__ void r8B_regs(float4* v, float h0, float sc){
    float a[8];
    {   Coef k = mkcoef(h0);
        #pragma unroll
        for (int n = 0; n < 8; n++) a[n] = v[n].x;
        r8B_apply(a, k);
        #pragma unroll
        for (int n = 0; n < 8; n++) v[n].x = a[n];
    }
    {   Coef k = mkcoef(h0 + sc);
        #pragma unroll
        for (int n = 0; n < 8; n++) a[n] = v[n].y;
        r8B_apply(a, k);
        #pragma unroll
        for (int n = 0; n < 8; n++) v[n].y = a[n];
    }
    {   Coef k = mkcoef(h0 + 2.f * sc);
        #pragma unroll
        for (int n = 0; n < 8; n++) a[n] = v[n].z;
        r8B_apply(a, k);
        #pragma unroll
        for (int n = 0; n < 8; n++) v[n].z = a[n];
    }
    {   Coef k = mkcoef(h0 + 3.f * sc);
        #pragma unroll
        for (int n = 0; n < 8; n++) a[n] = v[n].w;
        r8B_apply(a, k);
        #pragma unroll
        for (int n = 0; n < 8; n++) v[n].w = a[n];
    }
}

template<int B>
__device__ __forceinline__ void r8B(float4* tile, int t, int R0){
    const int   mtop = (1 << (8 - B)) - 1;
    const int   base = ((t >> B) << (B + 3)) | (t & ((1 << B) - 1));
    const float sc   = PI / (float)(1 << (21 - B));
    int   rl = (int)(__brev((unsigned)base) >> 21);
    int   jb = ((rl & mtop) << 11) + R0;
    float h0 = (float)jb * sc;
    int idx[8]; float4 v[8];
    #pragma unroll
    for (int n = 0; n < 8; n++){ idx[n] = swz(base + (n << B)); v[n] = tile[idx[n]]; }
    r8B_regs(v, h0, sc);
    #pragma unroll
    for (int n = 0; n < 8; n++) tile[idx[n]] = v[n];
}

// ================= Pass A: stages 1..11 =================
// Phases: [LDG + stages1-3 (const twiddles)] -> r8A<3> -> r8A<6> -> [r4(10,11) + transpose STG]
__global__ void __launch_bounds__(256) fftA(const float4* __restrict__ x4){
    __shared__ float4 tile[2048];
    const int t   = threadIdx.x;
    const int lb4 = blockIdx.x;

    // ---- round 1: rows 8t..8t+7, stages 1-3 fully in registers ----
    {
        float4 v[8];
        #pragma unroll
        for (int n = 0; n < 8; n++){
            int r = (t << 3) | n;
            int T = (int)(__brev((unsigned)r) >> 21);
            v[n] = x4[(T << 9) + lb4];
        }
        float4 S[8];
#define R1(L) { \
        float a0=fabsf(v[0].L+v[1].L), a1=fabsf(v[0].L-v[1].L); \
        float a2=fabsf(v[2].L+v[3].L), a3=fabsf(v[2].L-v[3].L); \
        float a4=fabsf(v[4].L+v[5].L), a5=fabsf(v[4].L-v[5].L); \
        float a6=fabsf(v[6].L+v[7].L), a7=fabsf(v[6].L-v[7].L); \
        float s0=a0+a2, d0=a0-a2; float S0=s0*s0, S2=d0*d0; \
        float S1=fmaf(a1,a1,a3*a3);  float S3=S1; \
        float s4=a4+a6, d4=a4-a6; float S4=s4*s4, S6=d4*d4; \
        float S5=fmaf(a5,a5,a7*a7);  float S7=S5; \
        bfly(S0,S4,1.f); bfly(S1,S5,IR2); \
        float tz=S2+S6; S2=tz; S6=tz; \
        bfly(S3,S7,-IR2); \
        S[0].L=S0; S[1].L=S1; S[2].L=S2; S[3].L=S3; \
        S[4].L=S4; S[5].L=S5; S[6].L=S6; S[7].L=S7; }
        R1(x) R1(y) R1(z) R1(w)
#undef R1
        #pragma unroll
        for (int n = 0; n < 8; n++) tile[swz((t << 3) | n)] = S[n];
    }
    __syncwarp();                       // r8A<3> rows stay within warp slab

    r8A<3>(tile, t); __syncthreads();   // stages 4,5,6
    r8A<6>(tile, t); __syncthreads();   // stages 7,8,9

    // ---- final radix-4 (stages 10,11) fused with transpose-store to scratch ----
    {
        float* scr = (float*)g_scr;
        #pragma unroll
        for (int m = 0; m < 2; m++){
            int gb = t + (m << 8);                       // 0..511
            float h2 = (float)gb * (PI / 1024.f);
            float sH = sin_ap(h2), cH = sin_ap(PIH - h2);
            float c1 = fmaf(-2.f * sH, sH, 1.f);
            float msH = -sH;
            float4 v0 = tile[swz(gb)];
            float4 v1 = tile[swz(gb + 512)];
            float4 v2 = tile[swz(gb + 1024)];
            float4 v3 = tile[swz(gb + 1536)];
#define R4A(L) { bfly(v0.L, v1.L, c1); bfly(v2.L, v3.L, c1); \
                 bfly(v0.L, v2.L, cH); bfly(v1.L, v3.L, msH); }
            R4A(x) R4A(y) R4A(z) R4A(w)
#undef R4A
            // transpose scatter: scr[(r>>2)<<13 | (4*lb4+li)<<2 | (r&3)]
            #pragma unroll
            for (int kk = 0; kk < 4; kk++){
                int r = gb + (kk << 9);
                int a = ((r >> 2) << 13) + ((lb4 << 2) << 2) + (r & 3);
                const float4& vv = (kk == 0) ? v0 : (kk == 1) ? v1 : (kk == 2) ? v2 : v3;
                scr[a]      = vv.x;
                scr[a + 4]  = vv.y;
                scr[a + 8]  = vv.z;
                scr[a + 12] = vv.w;
            }
        }
    }
}

// ================= Pass B: stages 12..22 + sqrt + bit-reversed store =================
__global__ void __launch_bounds__(256) fftB(float4* __restrict__ out4){
    __shared__ float4 tile[2048];
    const int t  = threadIdx.x;
    const int g  = blockIdx.x;
    const int R0 = g << 2;
    const int w  = t >> 5, ln = t & 31;

    // round 1 (stages 12,13,14): register-forwarded load (rows t + 256n)
    {
        const float sc = PI / (float)(1 << 13);
        float h0 = (float)R0 * sc;
        float4 v[8];
        const float4* src = g_scr + ((long)g << 11) + t;
        #pragma unroll
        for (int n = 0; n < 8; n++) v[n] = src[n << 8];
        r8B_regs(v, h0, sc);
        #pragma unroll
        for (int n = 0; n < 8; n++) tile[swz(t + (n << 8))] = v[n];
    }
    __syncthreads();

    r8B<5>(tile, t, R0); __syncwarp();   // stages 15,16,17 (warp-local)
    r8B<2>(tile, t, R0); __syncwarp();   // stages 18,19,20 (warp-local)

    // final radix-4 (stages 21,22) + sqrt + bit-reversed scatter (warp-local groups)
    {
        const float hs = PI / (float)(1 << 21);
        #pragma unroll
        for (int m = 0; m < 2; m++){
            int gb   = (w << 6) | ln | (m << 5);
            int base = gb << 2;
            int i00 = swz(base), i01 = swz(base + 1), i10 = swz(base + 2), i11 = swz(base + 3);
            int rl = (int)(__brev((unsigned)base) >> 21);
            int jb = ((rl & 511) << 11) + R0;
            float h0 = (float)jb * hs;
            float4 v00 = tile[i00], v01 = tile[i01], v10 = tile[i10], v11 = tile[i11];
#define RLF(L, K) { float h = fmaf((float)K, hs, h0); \
            float sh = sin_ap(h), ch = sin_ap(PIH - h); \
            float c2 = fmaf(-2.f * sh, sh, 1.f); float msh = -sh; \
            bfly(v00.L, v10.L, c2); bfly(v01.L, v11.L, c2); \
            bfly(v00.L, v01.L, ch); bfly(v10.L, v11.L, msh); }
            RLF(x,0) RLF(y,1) RLF(z,2) RLF(w,3)
#undef RLF
#define SQ4(v) make_float4(sqrt_ap(fmaxf(v.x,0.f)), sqrt_ap(fmaxf(v.y,0.f)), \
                           sqrt_ap(fmaxf(v.z,0.f)), sqrt_ap(fmaxf(v.w,0.f)))
            out4[(((int)(__brev((unsigned)(base + 0)) >> 21)) << 9) + g] = SQ4(v00);
            out4[(((int)(__brev((unsigned)(base + 1)) >> 21)) << 9) + g] = SQ4(v01);
            out4[(((int)(__brev((unsigned)(base + 2)) >> 21)) << 9) + g] = SQ4(v10);
            out4[(((int)(__brev((unsigned)(base + 3)) >> 21)) << 9) + g] = SQ4(v11);
#undef SQ4
        }
    }
}

extern "C" void kernel_launch(void* const* d_in, const int* in_sizes, int n_in,
                              void* d_out, int out_size) {
    const float4* x4 = (const float4*)d_in[0];
    fftA<<<512, 256>>>(x4);
    fftB<<<512, 256>>>((float4*)d_out);
}